// round 1
// baseline (speedup 1.0000x reference)
#include <cuda_runtime.h>
#include <math.h>

#define BATCH 16
#define NN 1024
#define DD 128
#define NBLK 15
#define CNT (BATCH*NN)           // 16384 rows for BN stats
#define EPSV 1e-5f

// -------- scratch (no allocation allowed) --------
__device__ float g_buf0[BATCH*NN*DD];      // 8 MB
__device__ float g_buf1[BATCH*NN*DD];      // 8 MB
__device__ float g_hbuf[BATCH*NN*DD];      // 8 MB  (elu(bn(x1)))
__device__ float g_stats[(NBLK+2)*2*DD];   // [slot][sum|sumsq][128]
__device__ float g_pooled[BATCH*DD];
__device__ float g_den[BATCH];

// -------- zero stats (runs each graph replay) --------
__global__ void zero_stats_kernel() {
    for (int i = threadIdx.x; i < (NBLK+2)*2*DD; i += blockDim.x) g_stats[i] = 0.f;
}

// -------- conv1: x1 = inputs @ W1 + b1 ; x2 = 0 --------
__global__ void conv1_kernel(const float* __restrict__ inp,
                             const float* __restrict__ W1,
                             const float* __restrict__ b1) {
    int gid = blockIdx.x * blockDim.x + threadIdx.x;   // over B*N*D
    int row = gid >> 7;
    int c   = gid & 127;
    const float* x = inp + row * 3;
    float v = fmaf(x[0], W1[c], fmaf(x[1], W1[128 + c], fmaf(x[2], W1[256 + c], b1[c])));
    g_buf0[gid] = v;
    g_buf1[gid] = 0.f;
}

// -------- per-channel sum / sumsq over all (B,N) rows --------
__global__ void stats_kernel(const float* __restrict__ x, int slot) {
    int c = threadIdx.x & 127, half = threadIdx.x >> 7;
    int row0 = blockIdx.x * 128;                 // 128 CTAs x 128 rows = 16384
    float s = 0.f, q = 0.f;
    for (int i = half; i < 128; i += 2) {
        float v = x[(row0 + i) * DD + c];
        s += v; q += v * v;
    }
    __shared__ float ss[256], qq[256];
    ss[threadIdx.x] = s; qq[threadIdx.x] = q;
    __syncthreads();
    if (half == 0) {
        s += ss[c + 128]; q += qq[c + 128];
        atomicAdd(&g_stats[slot * 256 + c], s);
        atomicAdd(&g_stats[slot * 256 + 128 + c], q);
    }
}

// -------- h = elu(bn(x)) --------
__global__ void bnelu_kernel(const float* __restrict__ x,
                             const float* __restrict__ gam,
                             const float* __restrict__ bet, int slot) {
    int gid = blockIdx.x * blockDim.x + threadIdx.x;
    int c = gid & 127;
    float s = g_stats[slot * 256 + c], q = g_stats[slot * 256 + 128 + c];
    float mean = s * (1.f / CNT);
    float var  = q * (1.f / CNT) - mean * mean;
    float sc = gam[c] * rsqrtf(var + EPSV);
    float v = fmaf(sc, x[gid], bet[c] - mean * sc);
    g_hbuf[gid] = (v > 0.f) ? v : expm1f(v);
}

// -------- main fused GEMM: y = L_tile @ h ; z = y@Wk + bk ; x2 += z --------
// grid (8 mtiles, 16 batches), 256 threads, 128x128 tile, BK=16
#define SMEM_FLOATS (16384 + 16896 + 4224 + 4224)   // W_s + y_s + As(x2) + Bs(x2)
#define SMEM_BYTES  (SMEM_FLOATS * 4)

__global__ void __launch_bounds__(256, 1)
block_gemm(const float* __restrict__ h, float* __restrict__ xb,
           const float* __restrict__ Lmat, const float* __restrict__ Wk,
           const float* __restrict__ bk) {
    const int tid = threadIdx.x;
    const int tx = tid & 15, ty = tid >> 4;
    const int batch = blockIdx.y, mt = blockIdx.x;
    const float* Lb  = Lmat + ((size_t)batch << 20) + ((size_t)(mt << 7)) * NN;
    const float* hb  = h + ((size_t)batch << 17);
    float*       xbb = xb + ((size_t)batch << 17) + (size_t)(mt << 7) * DD;

    extern __shared__ float sm[];
    float* W_s = sm;                 // 128x128
    float* y_s = sm + 16384;         // 128x132
    float* As  = sm + 16384 + 16896; // 2 x [16][132] (stored transposed: [k][m])
    float* Bs  = As + 4224;          // 2 x [16][132]

    // stage Wk into SMEM (used only in epilogue)
    {
        const float4* W4 = (const float4*)Wk;
        float4* Ws4 = (float4*)W_s;
        #pragma unroll
        for (int i = 0; i < 16; i++) Ws4[tid + i * 256] = W4[tid + i * 256];
    }

    float acc[8][8];
    #pragma unroll
    for (int i = 0; i < 8; i++)
        #pragma unroll
        for (int j = 0; j < 8; j++) acc[i][j] = 0.f;

    // load-index decode (512 float4 per tile, 2 per thread)
    const int a_row0 = tid >> 2;            // 0..63
    const int a_row1 = a_row0 + 64;         // 64..127
    const int a_kq   = (tid & 3) * 4;       // k sub-offset 0,4,8,12
    const int b_r0   = tid >> 5;            // 0..7
    const int b_r1   = b_r0 + 8;            // 8..15
    const int b_c    = (tid & 31) * 4;      // 0..124

    float4 ra0, ra1, rb0, rb1;

    // prologue: tile k0 = 0 -> buffer 0
    ra0 = *(const float4*)&Lb[(size_t)a_row0 * NN + a_kq];
    ra1 = *(const float4*)&Lb[(size_t)a_row1 * NN + a_kq];
    rb0 = *(const float4*)&hb[b_r0 * DD + b_c];
    rb1 = *(const float4*)&hb[b_r1 * DD + b_c];
    {
        float* A0 = As; float* B0 = Bs;
        A0[(a_kq + 0) * 132 + a_row0] = ra0.x; A0[(a_kq + 1) * 132 + a_row0] = ra0.y;
        A0[(a_kq + 2) * 132 + a_row0] = ra0.z; A0[(a_kq + 3) * 132 + a_row0] = ra0.w;
        A0[(a_kq + 0) * 132 + a_row1] = ra1.x; A0[(a_kq + 1) * 132 + a_row1] = ra1.y;
        A0[(a_kq + 2) * 132 + a_row1] = ra1.z; A0[(a_kq + 3) * 132 + a_row1] = ra1.w;
        B0[b_r0 * 132 + b_c + 0] = rb0.x; B0[b_r0 * 132 + b_c + 1] = rb0.y;
        B0[b_r0 * 132 + b_c + 2] = rb0.z; B0[b_r0 * 132 + b_c + 3] = rb0.w;
        B0[b_r1 * 132 + b_c + 0] = rb1.x; B0[b_r1 * 132 + b_c + 1] = rb1.y;
        B0[b_r1 * 132 + b_c + 2] = rb1.z; B0[b_r1 * 132 + b_c + 3] = rb1.w;
    }
    __syncthreads();

    for (int kt = 0; kt < 64; kt++) {
        const float* Ac = As + (kt & 1) * 2112;
        const float* Bc = Bs + (kt & 1) * 2112;
        if (kt < 63) {
            int k0 = (kt + 1) * 16;
            ra0 = *(const float4*)&Lb[(size_t)a_row0 * NN + k0 + a_kq];
            ra1 = *(const float4*)&Lb[(size_t)a_row1 * NN + k0 + a_kq];
            rb0 = *(const float4*)&hb[(k0 + b_r0) * DD + b_c];
            rb1 = *(const float4*)&hb[(k0 + b_r1) * DD + b_c];
        }
        #pragma unroll
        for (int kk = 0; kk < 16; kk++) {
            float4 a0 = *(const float4*)&Ac[kk * 132 + ty * 4];
            float4 a1 = *(const float4*)&Ac[kk * 132 + 64 + ty * 4];
            float4 b0 = *(const float4*)&Bc[kk * 132 + tx * 4];
            float4 b1 = *(const float4*)&Bc[kk * 132 + 64 + tx * 4];
            float av[8] = {a0.x, a0.y, a0.z, a0.w, a1.x, a1.y, a1.z, a1.w};
            float bv[8] = {b0.x, b0.y, b0.z, b0.w, b1.x, b1.y, b1.z, b1.w};
            #pragma unroll
            for (int i = 0; i < 8; i++)
                #pragma unroll
                for (int j = 0; j < 8; j++)
                    acc[i][j] = fmaf(av[i], bv[j], acc[i][j]);
        }
        if (kt < 63) {
            float* An = As + ((kt + 1) & 1) * 2112;
            float* Bn = Bs + ((kt + 1) & 1) * 2112;
            An[(a_kq + 0) * 132 + a_row0] = ra0.x; An[(a_kq + 1) * 132 + a_row0] = ra0.y;
            An[(a_kq + 2) * 132 + a_row0] = ra0.z; An[(a_kq + 3) * 132 + a_row0] = ra0.w;
            An[(a_kq + 0) * 132 + a_row1] = ra1.x; An[(a_kq + 1) * 132 + a_row1] = ra1.y;
            An[(a_kq + 2) * 132 + a_row1] = ra1.z; An[(a_kq + 3) * 132 + a_row1] = ra1.w;
            Bn[b_r0 * 132 + b_c + 0] = rb0.x; Bn[b_r0 * 132 + b_c + 1] = rb0.y;
            Bn[b_r0 * 132 + b_c + 2] = rb0.z; Bn[b_r0 * 132 + b_c + 3] = rb0.w;
            Bn[b_r1 * 132 + b_c + 0] = rb1.x; Bn[b_r1 * 132 + b_c + 1] = rb1.y;
            Bn[b_r1 * 132 + b_c + 2] = rb1.z; Bn[b_r1 * 132 + b_c + 3] = rb1.w;
        }
        __syncthreads();
    }

    // --- epilogue: y -> SMEM, z = y @ Wk, x2 += z + bk ---
    int rI[8];
    #pragma unroll
    for (int i = 0; i < 8; i++) rI[i] = (i < 4) ? (ty * 4 + i) : (64 + ty * 4 + i - 4);

    #pragma unroll
    for (int i = 0; i < 8; i++) {
        *(float4*)&y_s[rI[i] * 132 + tx * 4] =
            make_float4(acc[i][0], acc[i][1], acc[i][2], acc[i][3]);
        *(float4*)&y_s[rI[i] * 132 + 64 + tx * 4] =
            make_float4(acc[i][4], acc[i][5], acc[i][6], acc[i][7]);
    }
    __syncthreads();

    float z[8][8];
    #pragma unroll
    for (int i = 0; i < 8; i++)
        #pragma unroll
        for (int j = 0; j < 8; j++) z[i][j] = 0.f;

    #pragma unroll 4
    for (int n = 0; n < 128; n++) {
        float4 w0 = *(const float4*)&W_s[n * 128 + tx * 4];
        float4 w1 = *(const float4*)&W_s[n * 128 + 64 + tx * 4];
        #pragma unroll
        for (int i = 0; i < 8; i++) {
            float yv = y_s[rI[i] * 132 + n];
            z[i][0] = fmaf(yv, w0.x, z[i][0]);
            z[i][1] = fmaf(yv, w0.y, z[i][1]);
            z[i][2] = fmaf(yv, w0.z, z[i][2]);
            z[i][3] = fmaf(yv, w0.w, z[i][3]);
            z[i][4] = fmaf(yv, w1.x, z[i][4]);
            z[i][5] = fmaf(yv, w1.y, z[i][5]);
            z[i][6] = fmaf(yv, w1.z, z[i][6]);
            z[i][7] = fmaf(yv, w1.w, z[i][7]);
        }
    }

    float4 bb0 = *(const float4*)&bk[tx * 4];
    float4 bb1 = *(const float4*)&bk[64 + tx * 4];
    #pragma unroll
    for (int i = 0; i < 8; i++) {
        int r = rI[i];
        float4 o0 = *(float4*)&xbb[r * DD + tx * 4];
        o0.x += z[i][0] + bb0.x; o0.y += z[i][1] + bb0.y;
        o0.z += z[i][2] + bb0.z; o0.w += z[i][3] + bb0.w;
        *(float4*)&xbb[r * DD + tx * 4] = o0;
        float4 o1 = *(float4*)&xbb[r * DD + 64 + tx * 4];
        o1.x += z[i][4] + bb1.x; o1.y += z[i][5] + bb1.y;
        o1.z += z[i][6] + bb1.z; o1.w += z[i][7] + bb1.w;
        *(float4*)&xbb[r * DD + 64 + tx * 4] = o1;
    }
}

// -------- masked pooled elu(bn1(x1)+bn2(x2)) -> g_pooled, g_den --------
__global__ void pool_kernel(const float* __restrict__ xa, const float* __restrict__ xb,
                            const float* __restrict__ mask,
                            const float* __restrict__ g1, const float* __restrict__ be1,
                            const float* __restrict__ g2, const float* __restrict__ be2) {
    int b = blockIdx.x;
    int t = threadIdx.x;
    int c = t & 127, half = t >> 7;
    __shared__ float s1[128], t1s[128], s2[128], t2s[128];
    if (t < 128) {
        float s = g_stats[NBLK * 256 + t], q = g_stats[NBLK * 256 + 128 + t];
        float mean = s * (1.f / CNT), var = q * (1.f / CNT) - mean * mean;
        float sc = g1[t] * rsqrtf(var + EPSV);
        s1[t] = sc; t1s[t] = be1[t] - mean * sc;
        s = g_stats[(NBLK + 1) * 256 + t]; q = g_stats[(NBLK + 1) * 256 + 128 + t];
        mean = s * (1.f / CNT); var = q * (1.f / CNT) - mean * mean;
        sc = g2[t] * rsqrtf(var + EPSV);
        s2[t] = sc; t2s[t] = be2[t] - mean * sc;
    }
    __syncthreads();
    float acc = 0.f, msum = 0.f;
    for (int r = half; r < NN; r += 2) {
        float m = mask[b * NN + r];
        float v = fmaf(s1[c], xa[(b * NN + r) * DD + c], t1s[c]) +
                  fmaf(s2[c], xb[(b * NN + r) * DD + c], t2s[c]);
        v = (v > 0.f) ? v : expm1f(v);
        acc += m * v;
        if (c == 0) msum += m;
    }
    __shared__ float red[256];
    red[t] = acc;
    __syncthreads();
    if (half == 0) g_pooled[b * DD + c] = red[c] + red[c + 128];
    __syncthreads();
    red[t] = (c == 0) ? msum : 0.f;
    __syncthreads();
    if (t == 0) g_den[b] = red[0] + red[128];
}

// -------- out = (pooled @ W2)/den + b2 --------
__global__ void out_kernel(const float* __restrict__ W2, const float* __restrict__ b2,
                           float* __restrict__ out) {
    int b = blockIdx.x, d = threadIdx.x;   // 128 threads
    __shared__ float p[128];
    p[d] = g_pooled[b * DD + d];
    __syncthreads();
    float inv = 1.f / g_den[b];
    float accv = 0.f;
    #pragma unroll 4
    for (int c = 0; c < 128; c++) accv = fmaf(p[c], W2[c * 128 + d], accv);
    out[b * 128 + d] = accv * inv + b2[d];
}

extern "C" void kernel_launch(void* const* d_in, const int* in_sizes, int n_in,
                              void* d_out, int out_size) {
    const float* inputs = (const float*)d_in[0];
    const float* Lmat   = (const float*)d_in[1];
    const float* mask   = (const float*)d_in[2];
    const float* W1     = (const float*)d_in[3];
    const float* b1     = (const float*)d_in[4];
    const float* Wb     = (const float*)d_in[5];
    const float* bb     = (const float*)d_in[6];
    const float* gb     = (const float*)d_in[7];
    const float* beb    = (const float*)d_in[8];
    const float* g1     = (const float*)d_in[9];
    const float* be1    = (const float*)d_in[10];
    const float* g2     = (const float*)d_in[11];
    const float* be2    = (const float*)d_in[12];
    const float* W2     = (const float*)d_in[13];
    const float* b2     = (const float*)d_in[14];
    float* out = (float*)d_out;

    float *buf0, *buf1, *hbuf;
    cudaGetSymbolAddress((void**)&buf0, g_buf0);
    cudaGetSymbolAddress((void**)&buf1, g_buf1);
    cudaGetSymbolAddress((void**)&hbuf, g_hbuf);

    cudaFuncSetAttribute(block_gemm, cudaFuncAttributeMaxDynamicSharedMemorySize, SMEM_BYTES);

    zero_stats_kernel<<<1, 256>>>();
    conv1_kernel<<<(BATCH * NN * DD) / 256, 256>>>(inputs, W1, b1);

    float* pa = buf0;   // x1
    float* pb = buf1;   // x2
    for (int k = 0; k < NBLK; k++) {
        stats_kernel<<<128, 256>>>(pa, k);
        bnelu_kernel<<<(BATCH * NN * DD) / 256, 256>>>(pa, gb + k * DD, beb + k * DD, k);
        dim3 grid(8, 16);
        block_gemm<<<grid, 256, SMEM_BYTES>>>(hbuf, pb, Lmat, Wb + k * DD * DD, bb + k * DD);
        float* tmp = pa; pa = pb; pb = tmp;
    }
    stats_kernel<<<128, 256>>>(pa, NBLK);
    stats_kernel<<<128, 256>>>(pb, NBLK + 1);
    pool_kernel<<<BATCH, 256>>>(pa, pb, mask, g1, be1, g2, be2);
    out_kernel<<<BATCH, 128>>>(W2, b2, out);
}

// round 2
// speedup vs baseline: 1.0092x; 1.0092x over previous
#include <cuda_runtime.h>
#include <math.h>

#define BATCH 16
#define NN 1024
#define DD 128
#define NBLK 15
#define CNT (BATCH*NN)           // 16384 rows for BN stats
#define EPSV 1e-5f

// -------- scratch (no allocation allowed) --------
__device__ float g_buf0[BATCH*NN*DD];      // 8 MB
__device__ float g_buf1[BATCH*NN*DD];      // 8 MB
__device__ float g_hbuf[BATCH*NN*DD];      // 8 MB  (elu(bn(x1)))
__device__ float g_stats[(NBLK+2)*2*DD];   // [slot][sum|sumsq][128]
__device__ float g_pooled[BATCH*DD];
__device__ float g_den[BATCH];

// -------- zero stats (runs each graph replay) --------
__global__ void zero_stats_kernel() {
    for (int i = threadIdx.x; i < (NBLK+2)*2*DD; i += blockDim.x) g_stats[i] = 0.f;
}

// -------- conv1: x1 = inputs @ W1 + b1 ; x2 = 0 --------
__global__ void conv1_kernel(const float* __restrict__ inp,
                             const float* __restrict__ W1,
                             const float* __restrict__ b1) {
    int gid = blockIdx.x * blockDim.x + threadIdx.x;   // over B*N*D
    int row = gid >> 7;
    int c   = gid & 127;
    const float* x = inp + row * 3;
    float v = fmaf(x[0], W1[c], fmaf(x[1], W1[128 + c], fmaf(x[2], W1[256 + c], b1[c])));
    g_buf0[gid] = v;
    g_buf1[gid] = 0.f;
}

// -------- per-channel sum / sumsq over all (B,N) rows --------
__global__ void stats_kernel(const float* __restrict__ x, int slot) {
    int c = threadIdx.x & 127, half = threadIdx.x >> 7;
    int row0 = blockIdx.x * 128;                 // 128 CTAs x 128 rows = 16384
    float s = 0.f, q = 0.f;
    for (int i = half; i < 128; i += 2) {
        float v = x[(row0 + i) * DD + c];
        s += v; q += v * v;
    }
    __shared__ float ss[256], qq[256];
    ss[threadIdx.x] = s; qq[threadIdx.x] = q;
    __syncthreads();
    if (half == 0) {
        s += ss[c + 128]; q += qq[c + 128];
        atomicAdd(&g_stats[slot * 256 + c], s);
        atomicAdd(&g_stats[slot * 256 + 128 + c], q);
    }
}

// -------- h = elu(bn(x)) --------
__global__ void bnelu_kernel(const float* __restrict__ x,
                             const float* __restrict__ gam,
                             const float* __restrict__ bet, int slot) {
    int gid = blockIdx.x * blockDim.x + threadIdx.x;
    int c = gid & 127;
    float s = g_stats[slot * 256 + c], q = g_stats[slot * 256 + 128 + c];
    float mean = s * (1.f / CNT);
    float var  = q * (1.f / CNT) - mean * mean;
    float sc = gam[c] * rsqrtf(var + EPSV);
    float v = fmaf(sc, x[gid], bet[c] - mean * sc);
    g_hbuf[gid] = (v > 0.f) ? v : expm1f(v);
}

// -------- main fused GEMM: y = L_tile @ h ; z = y@Wk + bk ; x2 += z --------
// grid (8 mtiles, 16 batches), 256 threads, 128x128 tile, BK=16
#define SMEM_FLOATS (16384 + 16896 + 4224 + 4224)   // W_s + y_s + As(x2) + Bs(x2)
#define SMEM_BYTES  (SMEM_FLOATS * 4)

__global__ void __launch_bounds__(256, 1)
block_gemm(const float* __restrict__ h, float* __restrict__ xb,
           const float* __restrict__ Lmat, const float* __restrict__ Wk,
           const float* __restrict__ bk) {
    const int tid = threadIdx.x;
    const int tx = tid & 15, ty = tid >> 4;
    const int batch = blockIdx.y, mt = blockIdx.x;
    const float* Lb  = Lmat + ((size_t)batch << 20) + ((size_t)(mt << 7)) * NN;
    const float* hb  = h + ((size_t)batch << 17);
    float*       xbb = xb + ((size_t)batch << 17) + (size_t)(mt << 7) * DD;

    extern __shared__ float sm[];
    float* W_s = sm;                 // 128x128
    float* y_s = sm + 16384;         // 128x132
    float* As  = sm + 16384 + 16896; // 2 x [16][132] (stored transposed: [k][m])
    float* Bs  = As + 4224;          // 2 x [16][132]

    // stage Wk into SMEM (used only in epilogue)
    {
        const float4* W4 = (const float4*)Wk;
        float4* Ws4 = (float4*)W_s;
        #pragma unroll
        for (int i = 0; i < 16; i++) Ws4[tid + i * 256] = W4[tid + i * 256];
    }

    float acc[8][8];
    #pragma unroll
    for (int i = 0; i < 8; i++)
        #pragma unroll
        for (int j = 0; j < 8; j++) acc[i][j] = 0.f;

    // load-index decode (512 float4 per tile, 2 per thread)
    const int a_row0 = tid >> 2;            // 0..63
    const int a_row1 = a_row0 + 64;         // 64..127
    const int a_kq   = (tid & 3) * 4;       // k sub-offset 0,4,8,12
    const int b_r0   = tid >> 5;            // 0..7
    const int b_r1   = b_r0 + 8;            // 8..15
    const int b_c    = (tid & 31) * 4;      // 0..124

    float4 ra0, ra1, rb0, rb1;

    // prologue: tile k0 = 0 -> buffer 0
    ra0 = *(const float4*)&Lb[(size_t)a_row0 * NN + a_kq];
    ra1 = *(const float4*)&Lb[(size_t)a_row1 * NN + a_kq];
    rb0 = *(const float4*)&hb[b_r0 * DD + b_c];
    rb1 = *(const float4*)&hb[b_r1 * DD + b_c];
    {
        float* A0 = As; float* B0 = Bs;
        A0[(a_kq + 0) * 132 + a_row0] = ra0.x; A0[(a_kq + 1) * 132 + a_row0] = ra0.y;
        A0[(a_kq + 2) * 132 + a_row0] = ra0.z; A0[(a_kq + 3) * 132 + a_row0] = ra0.w;
        A0[(a_kq + 0) * 132 + a_row1] = ra1.x; A0[(a_kq + 1) * 132 + a_row1] = ra1.y;
        A0[(a_kq + 2) * 132 + a_row1] = ra1.z; A0[(a_kq + 3) * 132 + a_row1] = ra1.w;
        B0[b_r0 * 132 + b_c + 0] = rb0.x; B0[b_r0 * 132 + b_c + 1] = rb0.y;
        B0[b_r0 * 132 + b_c + 2] = rb0.z; B0[b_r0 * 132 + b_c + 3] = rb0.w;
        B0[b_r1 * 132 + b_c + 0] = rb1.x; B0[b_r1 * 132 + b_c + 1] = rb1.y;
        B0[b_r1 * 132 + b_c + 2] = rb1.z; B0[b_r1 * 132 + b_c + 3] = rb1.w;
    }
    __syncthreads();

    for (int kt = 0; kt < 64; kt++) {
        const float* Ac = As + (kt & 1) * 2112;
        const float* Bc = Bs + (kt & 1) * 2112;
        if (kt < 63) {
            int k0 = (kt + 1) * 16;
            ra0 = *(const float4*)&Lb[(size_t)a_row0 * NN + k0 + a_kq];
            ra1 = *(const float4*)&Lb[(size_t)a_row1 * NN + k0 + a_kq];
            rb0 = *(const float4*)&hb[(k0 + b_r0) * DD + b_c];
            rb1 = *(const float4*)&hb[(k0 + b_r1) * DD + b_c];
        }
        #pragma unroll
        for (int kk = 0; kk < 16; kk++) {
            float4 a0 = *(const float4*)&Ac[kk * 132 + ty * 4];
            float4 a1 = *(const float4*)&Ac[kk * 132 + 64 + ty * 4];
            float4 b0 = *(const float4*)&Bc[kk * 132 + tx * 4];
            float4 b1 = *(const float4*)&Bc[kk * 132 + 64 + tx * 4];
            float av[8] = {a0.x, a0.y, a0.z, a0.w, a1.x, a1.y, a1.z, a1.w};
            float bv[8] = {b0.x, b0.y, b0.z, b0.w, b1.x, b1.y, b1.z, b1.w};
            #pragma unroll
            for (int i = 0; i < 8; i++)
                #pragma unroll
                for (int j = 0; j < 8; j++)
                    acc[i][j] = fmaf(av[i], bv[j], acc[i][j]);
        }
        if (kt < 63) {
            float* An = As + ((kt + 1) & 1) * 2112;
            float* Bn = Bs + ((kt + 1) & 1) * 2112;
            An[(a_kq + 0) * 132 + a_row0] = ra0.x; An[(a_kq + 1) * 132 + a_row0] = ra0.y;
            An[(a_kq + 2) * 132 + a_row0] = ra0.z; An[(a_kq + 3) * 132 + a_row0] = ra0.w;
            An[(a_kq + 0) * 132 + a_row1] = ra1.x; An[(a_kq + 1) * 132 + a_row1] = ra1.y;
            An[(a_kq + 2) * 132 + a_row1] = ra1.z; An[(a_kq + 3) * 132 + a_row1] = ra1.w;
            Bn[b_r0 * 132 + b_c + 0] = rb0.x; Bn[b_r0 * 132 + b_c + 1] = rb0.y;
            Bn[b_r0 * 132 + b_c + 2] = rb0.z; Bn[b_r0 * 132 + b_c + 3] = rb0.w;
            Bn[b_r1 * 132 + b_c + 0] = rb1.x; Bn[b_r1 * 132 + b_c + 1] = rb1.y;
            Bn[b_r1 * 132 + b_c + 2] = rb1.z; Bn[b_r1 * 132 + b_c + 3] = rb1.w;
        }
        __syncthreads();
    }

    // --- epilogue: y -> SMEM, z = y @ Wk, x2 += z + bk ---
    int rI[8];
    #pragma unroll
    for (int i = 0; i < 8; i++) rI[i] = (i < 4) ? (ty * 4 + i) : (64 + ty * 4 + i - 4);

    #pragma unroll
    for (int i = 0; i < 8; i++) {
        *(float4*)&y_s[rI[i] * 132 + tx * 4] =
            make_float4(acc[i][0], acc[i][1], acc[i][2], acc[i][3]);
        *(float4*)&y_s[rI[i] * 132 + 64 + tx * 4] =
            make_float4(acc[i][4], acc[i][5], acc[i][6], acc[i][7]);
    }
    __syncthreads();

    float z[8][8];
    #pragma unroll
    for (int i = 0; i < 8; i++)
        #pragma unroll
        for (int j = 0; j < 8; j++) z[i][j] = 0.f;

    #pragma unroll 4
    for (int n = 0; n < 128; n++) {
        float4 w0 = *(const float4*)&W_s[n * 128 + tx * 4];
        float4 w1 = *(const float4*)&W_s[n * 128 + 64 + tx * 4];
        #pragma unroll
        for (int i = 0; i < 8; i++) {
            float yv = y_s[rI[i] * 132 + n];
            z[i][0] = fmaf(yv, w0.x, z[i][0]);
            z[i][1] = fmaf(yv, w0.y, z[i][1]);
            z[i][2] = fmaf(yv, w0.z, z[i][2]);
            z[i][3] = fmaf(yv, w0.w, z[i][3]);
            z[i][4] = fmaf(yv, w1.x, z[i][4]);
            z[i][5] = fmaf(yv, w1.y, z[i][5]);
            z[i][6] = fmaf(yv, w1.z, z[i][6]);
            z[i][7] = fmaf(yv, w1.w, z[i][7]);
        }
    }

    float4 bb0 = *(const float4*)&bk[tx * 4];
    float4 bb1 = *(const float4*)&bk[64 + tx * 4];
    #pragma unroll
    for (int i = 0; i < 8; i++) {
        int r = rI[i];
        float4 o0 = *(float4*)&xbb[r * DD + tx * 4];
        o0.x += z[i][0] + bb0.x; o0.y += z[i][1] + bb0.y;
        o0.z += z[i][2] + bb0.z; o0.w += z[i][3] + bb0.w;
        *(float4*)&xbb[r * DD + tx * 4] = o0;
        float4 o1 = *(float4*)&xbb[r * DD + 64 + tx * 4];
        o1.x += z[i][4] + bb1.x; o1.y += z[i][5] + bb1.y;
        o1.z += z[i][6] + bb1.z; o1.w += z[i][7] + bb1.w;
        *(float4*)&xbb[r * DD + 64 + tx * 4] = o1;
    }
}

// -------- masked pooled elu(bn1(x1)+bn2(x2)) -> g_pooled, g_den --------
__global__ void pool_kernel(const float* __restrict__ xa, const float* __restrict__ xb,
                            const float* __restrict__ mask,
                            const float* __restrict__ g1, const float* __restrict__ be1,
                            const float* __restrict__ g2, const float* __restrict__ be2) {
    int b = blockIdx.x;
    int t = threadIdx.x;
    int c = t & 127, half = t >> 7;
    __shared__ float s1[128], t1s[128], s2[128], t2s[128];
    if (t < 128) {
        float s = g_stats[NBLK * 256 + t], q = g_stats[NBLK * 256 + 128 + t];
        float mean = s * (1.f / CNT), var = q * (1.f / CNT) - mean * mean;
        float sc = g1[t] * rsqrtf(var + EPSV);
        s1[t] = sc; t1s[t] = be1[t] - mean * sc;
        s = g_stats[(NBLK + 1) * 256 + t]; q = g_stats[(NBLK + 1) * 256 + 128 + t];
        mean = s * (1.f / CNT); var = q * (1.f / CNT) - mean * mean;
        sc = g2[t] * rsqrtf(var + EPSV);
        s2[t] = sc; t2s[t] = be2[t] - mean * sc;
    }
    __syncthreads();
    float acc = 0.f, msum = 0.f;
    for (int r = half; r < NN; r += 2) {
        float m = mask[b * NN + r];
        float v = fmaf(s1[c], xa[(b * NN + r) * DD + c], t1s[c]) +
                  fmaf(s2[c], xb[(b * NN + r) * DD + c], t2s[c]);
        v = (v > 0.f) ? v : expm1f(v);
        acc += m * v;
        if (c == 0) msum += m;
    }
    __shared__ float red[256];
    red[t] = acc;
    __syncthreads();
    if (half == 0) g_pooled[b * DD + c] = red[c] + red[c + 128];
    __syncthreads();
    red[t] = (c == 0) ? msum : 0.f;
    __syncthreads();
    if (t == 0) g_den[b] = red[0] + red[128];
}

// -------- out = (pooled @ W2)/den + b2 --------
__global__ void out_kernel(const float* __restrict__ W2, const float* __restrict__ b2,
                           float* __restrict__ out) {
    int b = blockIdx.x, d = threadIdx.x;   // 128 threads
    __shared__ float p[128];
    p[d] = g_pooled[b * DD + d];
    __syncthreads();
    float inv = 1.f / g_den[b];
    float accv = 0.f;
    #pragma unroll 4
    for (int c = 0; c < 128; c++) accv = fmaf(p[c], W2[c * 128 + d], accv);
    out[b * 128 + d] = accv * inv + b2[d];
}

extern "C" void kernel_launch(void* const* d_in, const int* in_sizes, int n_in,
                              void* d_out, int out_size) {
    const float* inputs = (const float*)d_in[0];
    const float* Lmat   = (const float*)d_in[1];
    const float* mask   = (const float*)d_in[2];
    const float* W1     = (const float*)d_in[3];
    const float* b1     = (const float*)d_in[4];
    const float* Wb     = (const float*)d_in[5];
    const float* bb     = (const float*)d_in[6];
    const float* gb     = (const float*)d_in[7];
    const float* beb    = (const float*)d_in[8];
    const float* g1     = (const float*)d_in[9];
    const float* be1    = (const float*)d_in[10];
    const float* g2     = (const float*)d_in[11];
    const float* be2    = (const float*)d_in[12];
    const float* W2     = (const float*)d_in[13];
    const float* b2     = (const float*)d_in[14];
    float* out = (float*)d_out;

    float *buf0, *buf1, *hbuf;
    cudaGetSymbolAddress((void**)&buf0, g_buf0);
    cudaGetSymbolAddress((void**)&buf1, g_buf1);
    cudaGetSymbolAddress((void**)&hbuf, g_hbuf);

    cudaFuncSetAttribute(block_gemm, cudaFuncAttributeMaxDynamicSharedMemorySize, SMEM_BYTES);

    zero_stats_kernel<<<1, 256>>>();
    conv1_kernel<<<(BATCH * NN * DD) / 256, 256>>>(inputs, W1, b1);

    float* pa = buf0;   // x1
    float* pb = buf1;   // x2
    for (int k = 0; k < NBLK; k++) {
        stats_kernel<<<128, 256>>>(pa, k);
        bnelu_kernel<<<(BATCH * NN * DD) / 256, 256>>>(pa, gb + k * DD, beb + k * DD, k);
        dim3 grid(8, 16);
        block_gemm<<<grid, 256, SMEM_BYTES>>>(hbuf, pb, Lmat, Wb + k * DD * DD, bb + k * DD);
        float* tmp = pa; pa = pb; pb = tmp;
    }
    stats_kernel<<<128, 256>>>(pa, NBLK);
    stats_kernel<<<128, 256>>>(pb, NBLK + 1);
    pool_kernel<<<BATCH, 256>>>(pa, pb, mask, g1, be1, g2, be2);
    out_kernel<<<BATCH, 128>>>(W2, b2, out);
}

// round 4
// speedup vs baseline: 1.6742x; 1.6589x over previous
#include <cuda_runtime.h>
#include <cuda_bf16.h>
#include <math.h>
#include <stdint.h>

#define BATCH 16
#define NN 1024
#define DD 128
#define NBLK 15
#define CNT (BATCH*NN)
#define EPSV 1e-5f

// ---------------- scratch (no allocation allowed) ----------------
__device__ float g_buf0[BATCH*NN*DD];                 // 8 MB (x ping)
__device__ float g_buf1[BATCH*NN*DD];                 // 8 MB (x pong)
__device__ __nv_bfloat16 g_lhi[(size_t)BATCH*NN*NN];  // 32 MB L hi
__device__ __nv_bfloat16 g_llo[(size_t)BATCH*NN*NN];  // 32 MB L lo
__device__ __nv_bfloat16 g_whi[BATCH*DD*NN];          // 4 MB  (h*Wk)^T hi  [b][d][n]
__device__ __nv_bfloat16 g_wlo[BATCH*DD*NN];          // 4 MB  (h*Wk)^T lo
__device__ float g_stats[17*2*DD];                    // [slot][sum|sumsq][128]
__device__ float g_pooled[BATCH*DD];
__device__ float g_den[BATCH];

// ---------------- helpers ----------------
__device__ __forceinline__ uint32_t smem_u32(const void* p) {
    uint32_t a;
    asm("{ .reg .u64 t; cvta.to.shared.u64 t, %1; cvt.u32.u64 %0, t; }"
        : "=r"(a) : "l"(p));
    return a;
}
#define SWZ(o) ((o) ^ (((o) >> 3) & 0x70))

__device__ __forceinline__ void ldsm4(uint32_t* r, uint32_t a) {
    asm volatile("ldmatrix.sync.aligned.m8n8.x4.shared.b16 {%0,%1,%2,%3}, [%4];"
        : "=r"(r[0]), "=r"(r[1]), "=r"(r[2]), "=r"(r[3]) : "r"(a));
}
__device__ __forceinline__ void mma16816(float* c, const uint32_t* a,
                                         uint32_t b0, uint32_t b1) {
    asm volatile("mma.sync.aligned.m16n8k16.row.col.f32.bf16.bf16.f32 "
        "{%0,%1,%2,%3}, {%4,%5,%6,%7}, {%8,%9}, {%0,%1,%2,%3};"
        : "+f"(c[0]), "+f"(c[1]), "+f"(c[2]), "+f"(c[3])
        : "r"(a[0]), "r"(a[1]), "r"(a[2]), "r"(a[3]), "r"(b0), "r"(b1));
}

// ---------------- small kernels ----------------
__global__ void zero_stats_kernel() {
    for (int i = threadIdx.x; i < 17*2*DD; i += blockDim.x) g_stats[i] = 0.f;
}

__global__ void lconv_kernel(const float* __restrict__ L) {
    int g = blockIdx.x * 256 + threadIdx.x;      // float4 index over 16M floats
    float4 v = ((const float4*)L)[g];
    union { __nv_bfloat16 h[4]; uint2 u; } ph, pl;
    float f[4] = {v.x, v.y, v.z, v.w};
    #pragma unroll
    for (int i = 0; i < 4; i++) {
        __nv_bfloat16 hi = __float2bfloat16(f[i]);
        ph.h[i] = hi;
        pl.h[i] = __float2bfloat16(f[i] - __bfloat162float(hi));
    }
    ((uint2*)g_lhi)[g] = ph.u;
    ((uint2*)g_llo)[g] = pl.u;
}

__global__ void conv1_kernel(const float* __restrict__ inp,
                             const float* __restrict__ W1,
                             const float* __restrict__ b1) {
    int gid = blockIdx.x * blockDim.x + threadIdx.x;
    int row = gid >> 7, c = gid & 127;
    const float* x = inp + row * 3;
    float v = fmaf(x[0], W1[c], fmaf(x[1], W1[128 + c], fmaf(x[2], W1[256 + c], b1[c])));
    g_buf0[gid] = v;
    g_buf1[gid] = 0.f;
}

__global__ void stats_kernel(const float* __restrict__ x, int slot) {
    int c = threadIdx.x & 127, half = threadIdx.x >> 7;
    int row0 = blockIdx.x * 128;
    float s = 0.f, q = 0.f;
    for (int i = half; i < 128; i += 2) {
        float v = x[(row0 + i) * DD + c];
        s += v; q += v * v;
    }
    __shared__ float ss[256], qq[256];
    ss[threadIdx.x] = s; qq[threadIdx.x] = q;
    __syncthreads();
    if (half == 0) {
        s += ss[c + 128]; q += qq[c + 128];
        atomicAdd(&g_stats[slot * 256 + c], s);
        atomicAdd(&g_stats[slot * 256 + 128 + c], q);
    }
}

// ---------------- bnelu + h*Wk + transposed bf16 hi/lo write ----------------
#define BW_SMEM ((16384 + 16896) * 4)
__global__ void __launch_bounds__(256)
bnelu_hw(const float* __restrict__ x, const float* __restrict__ Wk,
         const float* __restrict__ gam, const float* __restrict__ bet, int slot) {
    extern __shared__ __align__(1024) float smf[];
    float* W_s = smf;           // 128x128
    float* h_s = smf + 16384;   // 128x132
    __shared__ float sc[128], tsh[128];
    const int tid = threadIdx.x, b = blockIdx.y, r0 = blockIdx.x * 128;
    const float* xb = x + ((size_t)b << 17) + (size_t)r0 * DD;

    { const float4* W4 = (const float4*)Wk; float4* Ws4 = (float4*)W_s;
      #pragma unroll
      for (int i = 0; i < 16; i++) Ws4[i * 256 + tid] = W4[i * 256 + tid]; }
    if (tid < 128) {
        float s = g_stats[slot * 256 + tid], q = g_stats[slot * 256 + 128 + tid];
        float mean = s * (1.f / CNT), var = q * (1.f / CNT) - mean * mean;
        float k = gam[tid] * rsqrtf(var + EPSV);
        sc[tid] = k; tsh[tid] = bet[tid] - mean * k;
    }
    __syncthreads();
    #pragma unroll 8
    for (int i = 0; i < 64; i++) {
        int idx = i * 256 + tid, c = idx & 127;
        float v = fmaf(sc[c], xb[idx], tsh[c]);
        h_s[(idx >> 7) * 132 + c] = (v > 0.f) ? v : expm1f(v);
    }
    __syncthreads();

    const int tx = tid & 15, ty = tid >> 4;
    int rI[8];
    #pragma unroll
    for (int i = 0; i < 8; i++) rI[i] = (i < 4) ? (ty * 4 + i) : (64 + ty * 4 + i - 4);
    float z[8][8];
    #pragma unroll
    for (int i = 0; i < 8; i++)
        #pragma unroll
        for (int j = 0; j < 8; j++) z[i][j] = 0.f;
    #pragma unroll 4
    for (int n = 0; n < 128; n++) {
        float4 w0 = *(const float4*)&W_s[n * 128 + tx * 4];
        float4 w1 = *(const float4*)&W_s[n * 128 + 64 + tx * 4];
        #pragma unroll
        for (int i = 0; i < 8; i++) {
            float yv = h_s[rI[i] * 132 + n];
            z[i][0] = fmaf(yv, w0.x, z[i][0]); z[i][1] = fmaf(yv, w0.y, z[i][1]);
            z[i][2] = fmaf(yv, w0.z, z[i][2]); z[i][3] = fmaf(yv, w0.w, z[i][3]);
            z[i][4] = fmaf(yv, w1.x, z[i][4]); z[i][5] = fmaf(yv, w1.y, z[i][5]);
            z[i][6] = fmaf(yv, w1.z, z[i][6]); z[i][7] = fmaf(yv, w1.w, z[i][7]);
        }
    }
    __syncthreads();
    #pragma unroll
    for (int i = 0; i < 8; i++) {
        *(float4*)&h_s[rI[i] * 132 + tx * 4] = make_float4(z[i][0], z[i][1], z[i][2], z[i][3]);
        *(float4*)&h_s[rI[i] * 132 + 64 + tx * 4] = make_float4(z[i][4], z[i][5], z[i][6], z[i][7]);
    }
    __syncthreads();
    const size_t obase = (size_t)b * (DD * NN) + r0;
    #pragma unroll 8
    for (int i = 0; i < 64; i++) {
        int idx = i * 256 + tid, c = idx >> 7, rr = idx & 127;
        float v = h_s[rr * 132 + c];
        __nv_bfloat16 hi = __float2bfloat16(v);
        g_whi[obase + (size_t)c * NN + rr] = hi;
        g_wlo[obase + (size_t)c * NN + rr] = __float2bfloat16(v - __bfloat162float(hi));
    }
}

// ---------------- warp-MMA big GEMM: x2 += L*(hW) + bk, fused stats ----------------
// grid (8, 16), 256 threads (8 warps). SMEM: 2 stages x 64KB (Ah/Al/Bh/Bl 16KB each)
#define MM_SMEM (2 * 65536)
__global__ void __launch_bounds__(256)
mma_gemm(float* __restrict__ xb, const float* __restrict__ bk, int slot) {
    extern __shared__ __align__(1024) char sm[];
    const uint32_t smb = smem_u32(sm);
    const int tid = threadIdx.x, w = tid >> 5, l = tid & 31;
    const int b = blockIdx.y, mt8 = blockIdx.x;

    const size_t aoff = (size_t)b * NN * NN + (size_t)mt8 * 128 * NN;
    const size_t boff = (size_t)b * (DD * NN);
    const __nv_bfloat16* srcp[4] = { g_lhi + aoff, g_llo + aoff,
                                     g_whi + boff, g_wlo + boff };

    auto load_stage = [&](int kc, int st) {
        uint32_t dst0 = smb + st * 65536;
        #pragma unroll
        for (int i = 0; i < 16; i++) {
            int c = i * 256 + tid;
            int mat = c >> 10, r = (c >> 3) & 127, q = c & 7;
            const __nv_bfloat16* s = srcp[mat] + (size_t)r * NN + kc * 64 + q * 8;
            uint32_t d = dst0 + mat * 16384 + SWZ(r * 128 + q * 16);
            asm volatile("cp.async.cg.shared.global [%0], [%1], 16;" :: "r"(d), "l"(s));
        }
        asm volatile("cp.async.commit_group;" ::: "memory");
    };

    float acc[2][8][4] = {};
    const int mwo = (w & 3) * 32, nwo = (w >> 2) * 64;
    const int aRow = l & 15;
    const int selB = l >> 4;                       // 0/1 -> +8 k cols
    const int bRow = (l & 7) + (((l >> 3) & 1) << 3);

    load_stage(0, 0);
    for (int kc = 0; kc < 16; kc++) {
        if (kc + 1 < 16) {
            load_stage(kc + 1, (kc + 1) & 1);
            asm volatile("cp.async.wait_group 1;" ::: "memory");
        } else {
            asm volatile("cp.async.wait_group 0;" ::: "memory");
        }
        __syncthreads();
        uint32_t sb = smb + (kc & 1) * 65536;
        #pragma unroll
        for (int t = 0; t < 4; t++) {
            const int kb = t * 32 + selB * 16;     // byte offset in 128B row
            uint32_t ah[2][4], al[2][4];
            #pragma unroll
            for (int m = 0; m < 2; m++) {
                uint32_t ro = (mwo + m * 16 + aRow) * 128 + kb;
                ldsm4(ah[m], sb + SWZ(ro));
                ldsm4(al[m], sb + 16384 + SWZ(ro));
            }
            #pragma unroll
            for (int ng = 0; ng < 4; ng++) {
                uint32_t bh[4], bl[4];
                uint32_t ro = (nwo + ng * 16 + bRow) * 128 + kb;
                ldsm4(bh, sb + 32768 + SWZ(ro));
                ldsm4(bl, sb + 49152 + SWZ(ro));
                #pragma unroll
                for (int m = 0; m < 2; m++) {
                    mma16816(acc[m][2*ng],   ah[m], bh[0], bh[2]);
                    mma16816(acc[m][2*ng],   al[m], bh[0], bh[2]);
                    mma16816(acc[m][2*ng],   ah[m], bl[0], bl[2]);
                    mma16816(acc[m][2*ng+1], ah[m], bh[1], bh[3]);
                    mma16816(acc[m][2*ng+1], al[m], bh[1], bh[3]);
                    mma16816(acc[m][2*ng+1], ah[m], bl[1], bl[3]);
                }
            }
        }
        __syncthreads();
    }

    // ---- epilogue: accums -> SMEM, then residual + bias + fused BN stats ----
    float* red = (float*)sm;                       // 128 x 132
    const int r4 = l >> 2, c2 = (l & 3) * 2;
    #pragma unroll
    for (int m = 0; m < 2; m++)
        #pragma unroll
        for (int nt = 0; nt < 8; nt++) {
            int row = mwo + m * 16 + r4, col = nwo + nt * 8 + c2;
            *(float2*)&red[row * 132 + col] = make_float2(acc[m][nt][0], acc[m][nt][1]);
            *(float2*)&red[(row + 8) * 132 + col] = make_float2(acc[m][nt][2], acc[m][nt][3]);
        }
    __syncthreads();

    float* xbb = xb + ((size_t)b << 17) + (size_t)mt8 * 128 * DD;
    const int cc = tid & 127;
    const float bkv = bk[cc];
    float s = 0.f, q = 0.f;
    #pragma unroll 8
    for (int i = 0; i < 64; i++) {
        int idx = i * 256 + tid;
        int row = idx >> 7;
        float o = xbb[idx] + red[row * 132 + cc] + bkv;
        xbb[idx] = o;
        s += o; q += o * o;
    }
    float* ss = (float*)(sm + 69632);
    float* qq = ss + 256;
    ss[tid] = s; qq[tid] = q;
    __syncthreads();
    if (tid < 128) {
        s = ss[tid] + ss[tid + 128];
        q = qq[tid] + qq[tid + 128];
        atomicAdd(&g_stats[slot * 256 + tid], s);
        atomicAdd(&g_stats[slot * 256 + 128 + tid], q);
    }
}

// ---------------- pool + output ----------------
__global__ void pool_kernel(const float* __restrict__ xa, const float* __restrict__ xb,
                            const float* __restrict__ mask,
                            const float* __restrict__ g1, const float* __restrict__ be1,
                            const float* __restrict__ g2, const float* __restrict__ be2,
                            int slot1, int slot2) {
    int b = blockIdx.x, t = threadIdx.x;
    int c = t & 127, half = t >> 7;
    __shared__ float s1[128], t1s[128], s2[128], t2s[128];
    if (t < 128) {
        float s = g_stats[slot1 * 256 + t], q = g_stats[slot1 * 256 + 128 + t];
        float mean = s * (1.f / CNT), var = q * (1.f / CNT) - mean * mean;
        float sc = g1[t] * rsqrtf(var + EPSV);
        s1[t] = sc; t1s[t] = be1[t] - mean * sc;
        s = g_stats[slot2 * 256 + t]; q = g_stats[slot2 * 256 + 128 + t];
        mean = s * (1.f / CNT); var = q * (1.f / CNT) - mean * mean;
        sc = g2[t] * rsqrtf(var + EPSV);
        s2[t] = sc; t2s[t] = be2[t] - mean * sc;
    }
    __syncthreads();
    float acc = 0.f, msum = 0.f;
    for (int r = half; r < NN; r += 2) {
        float m = mask[b * NN + r];
        float v = fmaf(s1[c], xa[(b * NN + r) * DD + c], t1s[c]) +
                  fmaf(s2[c], xb[(b * NN + r) * DD + c], t2s[c]);
        v = (v > 0.f) ? v : expm1f(v);
        acc += m * v;
        if (c == 0) msum += m;
    }
    __shared__ float red[256];
    red[t] = acc;
    __syncthreads();
    if (half == 0) g_pooled[b * DD + c] = red[c] + red[c + 128];
    __syncthreads();
    red[t] = (c == 0) ? msum : 0.f;
    __syncthreads();
    if (t == 0) g_den[b] = red[0] + red[128];
}

__global__ void out_kernel(const float* __restrict__ W2, const float* __restrict__ b2,
                           float* __restrict__ out) {
    int b = blockIdx.x, d = threadIdx.x;
    __shared__ float p[128];
    p[d] = g_pooled[b * DD + d];
    __syncthreads();
    float inv = 1.f / g_den[b];
    float accv = 0.f;
    #pragma unroll 4
    for (int c = 0; c < 128; c++) accv = fmaf(p[c], W2[c * 128 + d], accv);
    out[b * 128 + d] = accv * inv + b2[d];
}

// ---------------- host ----------------
extern "C" void kernel_launch(void* const* d_in, const int* in_sizes, int n_in,
                              void* d_out, int out_size) {
    const float* inputs = (const float*)d_in[0];
    const float* Lmat   = (const float*)d_in[1];
    const float* mask   = (const float*)d_in[2];
    const float* W1     = (const float*)d_in[3];
    const float* b1     = (const float*)d_in[4];
    const float* Wb     = (const float*)d_in[5];
    const float* bb     = (const float*)d_in[6];
    const float* gb     = (const float*)d_in[7];
    const float* beb    = (const float*)d_in[8];
    const float* g1     = (const float*)d_in[9];
    const float* be1    = (const float*)d_in[10];
    const float* g2     = (const float*)d_in[11];
    const float* be2    = (const float*)d_in[12];
    const float* W2     = (const float*)d_in[13];
    const float* b2     = (const float*)d_in[14];
    float* out = (float*)d_out;

    float *buf0, *buf1;
    cudaGetSymbolAddress((void**)&buf0, g_buf0);
    cudaGetSymbolAddress((void**)&buf1, g_buf1);

    cudaFuncSetAttribute(mma_gemm, cudaFuncAttributeMaxDynamicSharedMemorySize, MM_SMEM);
    cudaFuncSetAttribute(bnelu_hw, cudaFuncAttributeMaxDynamicSharedMemorySize, BW_SMEM);

    zero_stats_kernel<<<1, 256>>>();
    lconv_kernel<<<(BATCH * NN * NN) / 4 / 256, 256>>>(Lmat);
    conv1_kernel<<<(BATCH * NN * DD) / 256, 256>>>(inputs, W1, b1);
    stats_kernel<<<128, 256>>>(buf0, 0);

    float* pa = buf0;   // x1
    float* pb = buf1;   // x2
    for (int k = 0; k < NBLK; k++) {
        dim3 grid(8, 16);
        bnelu_hw<<<grid, 256, BW_SMEM>>>(pa, Wb + k * DD * DD, gb + k * DD, beb + k * DD, k);
        mma_gemm<<<grid, 256, MM_SMEM>>>(pb, bb + k * DD, k + 1);
        float* tmp = pa; pa = pb; pb = tmp;
    }
    // pa = x1_final (stats slot 15), pb = x2_final (stats slot 14)
    pool_kernel<<<BATCH, 256>>>(pa, pb, mask, g1, be1, g2, be2, NBLK, NBLK - 1);
    out_kernel<<<BATCH, 128>>>(W2, b2, out);
}

// round 5
// speedup vs baseline: 2.0405x; 1.2188x over previous
#include <cuda_runtime.h>
#include <cuda_bf16.h>
#include <math.h>
#include <stdint.h>

#define BATCH 16
#define NN 1024
#define DD 128
#define NBLK 15
#define CNT (BATCH*NN)
#define EPSV 1e-5f

// ---------------- scratch (no allocation allowed) ----------------
__device__ float g_buf0[BATCH*NN*DD];                 // 8 MB (x ping)
__device__ float g_buf1[BATCH*NN*DD];                 // 8 MB (x pong)
__device__ __nv_bfloat16 g_lhi[(size_t)BATCH*NN*NN];  // 32 MB L hi
__device__ __nv_bfloat16 g_llo[(size_t)BATCH*NN*NN];  // 32 MB L lo
__device__ __nv_bfloat16 g_whi[BATCH*DD*NN];          // 4 MB  (h*Wk)^T hi  [b][d][n]
__device__ __nv_bfloat16 g_wlo[BATCH*DD*NN];          // 4 MB  (h*Wk)^T lo
__device__ __nv_bfloat16 g_wthi[NBLK*DD*DD];          // W^T hi  [k][e][d]
__device__ __nv_bfloat16 g_wtlo[NBLK*DD*DD];          // W^T lo
__device__ float g_stats[17*2*DD];                    // [slot][sum|sumsq][128]
__device__ float g_pooled[BATCH*DD];
__device__ float g_den[BATCH];

// ---------------- helpers ----------------
__device__ __forceinline__ uint32_t smem_u32(const void* p) {
    uint32_t a;
    asm("{ .reg .u64 t; cvta.to.shared.u64 t, %1; cvt.u32.u64 %0, t; }"
        : "=r"(a) : "l"(p));
    return a;
}
#define SWZ(o) ((o) ^ (((o) >> 3) & 0x70))

__device__ __forceinline__ void ldsm4(uint32_t* r, uint32_t a) {
    asm volatile("ldmatrix.sync.aligned.m8n8.x4.shared.b16 {%0,%1,%2,%3}, [%4];"
        : "=r"(r[0]), "=r"(r[1]), "=r"(r[2]), "=r"(r[3]) : "r"(a));
}
__device__ __forceinline__ void mma16816(float* c, const uint32_t* a,
                                         uint32_t b0, uint32_t b1) {
    asm volatile("mma.sync.aligned.m16n8k16.row.col.f32.bf16.bf16.f32 "
        "{%0,%1,%2,%3}, {%4,%5,%6,%7}, {%8,%9}, {%0,%1,%2,%3};"
        : "+f"(c[0]), "+f"(c[1]), "+f"(c[2]), "+f"(c[3])
        : "r"(a[0]), "r"(a[1]), "r"(a[2]), "r"(a[3]), "r"(b0), "r"(b1));
}

// 48 MMAs for one 128x128x16 step, pass-major (dependency distance = 16 MMAs)
__device__ __forceinline__ void mma_step(float acc[2][8][4],
    const uint32_t ah[2][4], const uint32_t al[2][4],
    const uint32_t bh[4][4], const uint32_t bl[4][4]) {
    #pragma unroll
    for (int m = 0; m < 2; m++)
        #pragma unroll
        for (int ng = 0; ng < 4; ng++) {
            mma16816(acc[m][2*ng],   ah[m], bh[ng][0], bh[ng][2]);
            mma16816(acc[m][2*ng+1], ah[m], bh[ng][1], bh[ng][3]);
        }
    #pragma unroll
    for (int m = 0; m < 2; m++)
        #pragma unroll
        for (int ng = 0; ng < 4; ng++) {
            mma16816(acc[m][2*ng],   al[m], bh[ng][0], bh[ng][2]);
            mma16816(acc[m][2*ng+1], al[m], bh[ng][1], bh[ng][3]);
        }
    #pragma unroll
    for (int m = 0; m < 2; m++)
        #pragma unroll
        for (int ng = 0; ng < 4; ng++) {
            mma16816(acc[m][2*ng],   ah[m], bl[ng][0], bl[ng][2]);
            mma16816(acc[m][2*ng+1], ah[m], bl[ng][1], bl[ng][3]);
        }
}

// ---------------- small kernels ----------------
__global__ void zero_stats_kernel() {
    for (int i = threadIdx.x; i < 17*2*DD; i += blockDim.x) g_stats[i] = 0.f;
    for (int i = threadIdx.x; i < BATCH*DD; i += blockDim.x) g_pooled[i] = 0.f;
    if (threadIdx.x < BATCH) g_den[threadIdx.x] = 0.f;
}

__global__ void lconv_kernel(const float* __restrict__ L) {
    int g = blockIdx.x * 256 + threadIdx.x;
    float4 v = ((const float4*)L)[g];
    union { __nv_bfloat16 h[4]; uint2 u; } ph, pl;
    float f[4] = {v.x, v.y, v.z, v.w};
    #pragma unroll
    for (int i = 0; i < 4; i++) {
        __nv_bfloat16 hi = __float2bfloat16(f[i]);
        ph.h[i] = hi;
        pl.h[i] = __float2bfloat16(f[i] - __bfloat162float(hi));
    }
    ((uint2*)g_lhi)[g] = ph.u;
    ((uint2*)g_llo)[g] = pl.u;
}

__global__ void wprep_all(const float* __restrict__ Wb) {
    int k = blockIdx.x;
    const float* W = Wb + k * DD * DD;
    __nv_bfloat16* oh = g_wthi + k * DD * DD;
    __nv_bfloat16* ol = g_wtlo + k * DD * DD;
    for (int i = threadIdx.x; i < DD * DD; i += blockDim.x) {
        int e = i >> 7, d = i & 127;
        float v = W[d * DD + e];
        __nv_bfloat16 hi = __float2bfloat16(v);
        oh[i] = hi;
        ol[i] = __float2bfloat16(v - __bfloat162float(hi));
    }
}

__global__ void conv1_kernel(const float* __restrict__ inp,
                             const float* __restrict__ W1,
                             const float* __restrict__ b1) {
    int gid = blockIdx.x * blockDim.x + threadIdx.x;
    int row = gid >> 7, c = gid & 127;
    const float* x = inp + row * 3;
    float v = fmaf(x[0], W1[c], fmaf(x[1], W1[128 + c], fmaf(x[2], W1[256 + c], b1[c])));
    g_buf0[gid] = v;
    g_buf1[gid] = 0.f;
}

__global__ void stats_kernel(const float* __restrict__ x, int slot) {
    int c = threadIdx.x & 127, half = threadIdx.x >> 7;
    int row0 = blockIdx.x * 64;
    float s = 0.f, q = 0.f;
    for (int i = half; i < 64; i += 2) {
        float v = x[(row0 + i) * DD + c];
        s += v; q += v * v;
    }
    __shared__ float ss[256], qq[256];
    ss[threadIdx.x] = s; qq[threadIdx.x] = q;
    __syncthreads();
    if (half == 0) {
        s += ss[c + 128]; q += qq[c + 128];
        atomicAdd(&g_stats[slot * 256 + c], s);
        atomicAdd(&g_stats[slot * 256 + 128 + c], q);
    }
}

// ---------------- bnelu + (h*Wk)^T via tensor cores ----------------
// grid (8 node-tiles, 16 batches), 256 threads.
// SMEM: A = W^T hi/lo (4 x 16KB at 0), B = h hi/lo (4 x 16KB at 64K),
// then f32 staging 128x132 reuses [0, 67584).
#define BM_SMEM 131072
__global__ void __launch_bounds__(256)
bnelu_mma(const float* __restrict__ x, int blk,
          const float* __restrict__ gam, const float* __restrict__ bet, int slot) {
    extern __shared__ __align__(1024) char sm[];
    const uint32_t smb = smem_u32(sm);
    __shared__ float sc[128], tsh[128];
    const int tid = threadIdx.x, w = tid >> 5, l = tid & 31;
    const int b = blockIdx.y, nt = blockIdx.x;

    if (tid < 128) {
        float s = g_stats[slot * 256 + tid], q = g_stats[slot * 256 + 128 + tid];
        float mean = s * (1.f / CNT), var = q * (1.f / CNT) - mean * mean;
        float k = gam[tid] * rsqrtf(var + EPSV);
        sc[tid] = k; tsh[tid] = bet[tid] - mean * k;
    }

    // A slabs: W^T [e][d], two 64-d slabs, hi then lo
    const __nv_bfloat16* wth = g_wthi + blk * DD * DD;
    const __nv_bfloat16* wtl = g_wtlo + blk * DD * DD;
    #pragma unroll
    for (int i = 0; i < 8; i++) {
        int c = i * 256 + tid;                  // 16B chunk over 2048
        int e = c >> 4, ch = c & 15;
        uint32_t off = (uint32_t)(ch >> 3) * 16384 + SWZ(e * 128 + (ch & 7) * 16);
        *(float4*)(sm + off) = *(const float4*)(wth + e * 128 + ch * 8);
        *(float4*)(sm + 32768 + off) = *(const float4*)(wtl + e * 128 + ch * 8);
    }
    __syncthreads();   // sc/tsh ready

    // B slabs: h[n][d] = elu(bn(x)), split hi/lo
    const float* xb = x + ((size_t)b << 17) + (size_t)nt * 128 * DD;
    #pragma unroll 8
    for (int i = 0; i < 64; i++) {
        int idx = i * 256 + tid;
        int n = idx >> 7, d = idx & 127;
        float v = fmaf(sc[d], xb[idx], tsh[d]);
        v = (v > 0.f) ? v : expm1f(v);
        __nv_bfloat16 hi = __float2bfloat16(v);
        __nv_bfloat16 lo = __float2bfloat16(v - __bfloat162float(hi));
        uint32_t o = (uint32_t)(d >> 6) * 16384 + SWZ(n * 128 + (d & 63) * 2);
        *(__nv_bfloat16*)(sm + 65536 + o) = hi;
        *(__nv_bfloat16*)(sm + 65536 + 32768 + o) = lo;
    }
    __syncthreads();

    float acc[2][8][4] = {};
    const int mwo = (w & 3) * 32, nwo = (w >> 2) * 64;
    const int aRow = l & 15, selB = l >> 4;
    const int bRow = (l & 7) + (((l >> 3) & 1) << 3);

    #pragma unroll
    for (int ks = 0; ks < 2; ks++) {
        uint32_t Ah = smb + ks * 16384, Al = Ah + 32768;
        uint32_t Bh = smb + 65536 + ks * 16384, Bl = Bh + 32768;
        #pragma unroll
        for (int t = 0; t < 4; t++) {
            const int kb = t * 32 + selB * 16;
            uint32_t ah[2][4], al[2][4], bh[4][4], bl[4][4];
            #pragma unroll
            for (int m = 0; m < 2; m++) {
                uint32_t ro = (mwo + m * 16 + aRow) * 128 + kb;
                ldsm4(ah[m], Ah + SWZ(ro));
                ldsm4(al[m], Al + SWZ(ro));
            }
            #pragma unroll
            for (int ng = 0; ng < 4; ng++) {
                uint32_t ro = (nwo + ng * 16 + bRow) * 128 + kb;
                ldsm4(bh[ng], Bh + SWZ(ro));
                ldsm4(bl[ng], Bl + SWZ(ro));
            }
            mma_step(acc, ah, al, bh, bl);
        }
    }
    __syncthreads();   // all operand reads done before staging overwrites

    float* red = (float*)sm;                   // 128 x 132
    const int r4 = l >> 2, c2 = (l & 3) * 2;
    #pragma unroll
    for (int m = 0; m < 2; m++)
        #pragma unroll
        for (int ntile = 0; ntile < 8; ntile++) {
            int row = mwo + m * 16 + r4, col = nwo + ntile * 8 + c2;
            *(float2*)&red[row * 132 + col] = make_float2(acc[m][ntile][0], acc[m][ntile][1]);
            *(float2*)&red[(row + 8) * 132 + col] = make_float2(acc[m][ntile][2], acc[m][ntile][3]);
        }
    __syncthreads();

    const size_t obase = (size_t)b * (DD * NN) + (size_t)nt * 128;
    #pragma unroll 8
    for (int i = 0; i < 64; i++) {
        int idx = i * 256 + tid;
        int e = idx >> 7, n = idx & 127;
        float v = red[e * 132 + n];
        __nv_bfloat16 hi = __float2bfloat16(v);
        g_whi[obase + (size_t)e * NN + n] = hi;
        g_wlo[obase + (size_t)e * NN + n] = __float2bfloat16(v - __bfloat162float(hi));
    }
}

// ---------------- warp-MMA big GEMM: x2 += L*(hW) + bk, fused stats ----------------
#define MM_SMEM (2 * 65536)
__global__ void __launch_bounds__(256)
mma_gemm(float* __restrict__ xb, const float* __restrict__ bk, int slot) {
    extern __shared__ __align__(1024) char sm[];
    const uint32_t smb = smem_u32(sm);
    const int tid = threadIdx.x, w = tid >> 5, l = tid & 31;
    const int b = blockIdx.y, mt8 = blockIdx.x;

    const size_t aoff = (size_t)b * NN * NN + (size_t)mt8 * 128 * NN;
    const size_t boff = (size_t)b * (DD * NN);
    const __nv_bfloat16* srcp[4] = { g_lhi + aoff, g_llo + aoff,
                                     g_whi + boff, g_wlo + boff };

    auto load_stage = [&](int kc, int st) {
        uint32_t dst0 = smb + st * 65536;
        #pragma unroll
        for (int i = 0; i < 16; i++) {
            int c = i * 256 + tid;
            int mat = c >> 10, r = (c >> 3) & 127, q = c & 7;
            const __nv_bfloat16* s = srcp[mat] + (size_t)r * NN + kc * 64 + q * 8;
            uint32_t d = dst0 + mat * 16384 + SWZ(r * 128 + q * 16);
            asm volatile("cp.async.cg.shared.global [%0], [%1], 16;" :: "r"(d), "l"(s));
        }
        asm volatile("cp.async.commit_group;" ::: "memory");
    };

    float acc[2][8][4] = {};
    const int mwo = (w & 3) * 32, nwo = (w >> 2) * 64;
    const int aRow = l & 15, selB = l >> 4;
    const int bRow = (l & 7) + (((l >> 3) & 1) << 3);

    load_stage(0, 0);
    for (int kc = 0; kc < 16; kc++) {
        if (kc + 1 < 16) {
            load_stage(kc + 1, (kc + 1) & 1);
            asm volatile("cp.async.wait_group 1;" ::: "memory");
        } else {
            asm volatile("cp.async.wait_group 0;" ::: "memory");
        }
        __syncthreads();
        uint32_t sb = smb + (kc & 1) * 65536;
        #pragma unroll
        for (int t = 0; t < 4; t++) {
            const int kb = t * 32 + selB * 16;
            uint32_t ah[2][4], al[2][4], bh[4][4], bl[4][4];
            #pragma unroll
            for (int m = 0; m < 2; m++) {
                uint32_t ro = (mwo + m * 16 + aRow) * 128 + kb;
                ldsm4(ah[m], sb + SWZ(ro));
                ldsm4(al[m], sb + 16384 + SWZ(ro));
            }
            #pragma unroll
            for (int ng = 0; ng < 4; ng++) {
                uint32_t ro = (nwo + ng * 16 + bRow) * 128 + kb;
                ldsm4(bh[ng], sb + 32768 + SWZ(ro));
                ldsm4(bl[ng], sb + 49152 + SWZ(ro));
            }
            mma_step(acc, ah, al, bh, bl);
        }
        __syncthreads();
    }

    // ---- epilogue: accums -> SMEM, then residual + bias + fused BN stats ----
    float* red = (float*)sm;                       // 128 x 132
    const int r4 = l >> 2, c2 = (l & 3) * 2;
    #pragma unroll
    for (int m = 0; m < 2; m++)
        #pragma unroll
        for (int nt = 0; nt < 8; nt++) {
            int row = mwo + m * 16 + r4, col = nwo + nt * 8 + c2;
            *(float2*)&red[row * 132 + col] = make_float2(acc[m][nt][0], acc[m][nt][1]);
            *(float2*)&red[(row + 8) * 132 + col] = make_float2(acc[m][nt][2], acc[m][nt][3]);
        }
    __syncthreads();

    float* xbb = xb + ((size_t)b << 17) + (size_t)mt8 * 128 * DD;
    const int cc = tid & 127;
    const float bkv = bk[cc];
    float s = 0.f, q = 0.f;
    #pragma unroll 8
    for (int i = 0; i < 64; i++) {
        int idx = i * 256 + tid;
        int row = idx >> 7;
        float o = xbb[idx] + red[row * 132 + cc] + bkv;
        xbb[idx] = o;
        s += o; q += o * o;
    }
    float* ss = (float*)(sm + 69632);
    float* qq = ss + 256;
    ss[tid] = s; qq[tid] = q;
    __syncthreads();
    if (tid < 128) {
        s = ss[tid] + ss[tid + 128];
        q = qq[tid] + qq[tid + 128];
        atomicAdd(&g_stats[slot * 256 + tid], s);
        atomicAdd(&g_stats[slot * 256 + 128 + tid], q);
    }
}

// ---------------- pool (partial, atomics) + output ----------------
__global__ void pool_kernel(const float* __restrict__ xa, const float* __restrict__ xb,
                            const float* __restrict__ mask,
                            const float* __restrict__ g1, const float* __restrict__ be1,
                            const float* __restrict__ g2, const float* __restrict__ be2,
                            int slot1, int slot2) {
    int b = blockIdx.x, seg = blockIdx.y, t = threadIdx.x;
    int c = t & 127, half = t >> 7;
    __shared__ float s1[128], t1s[128], s2[128], t2s[128];
    if (t < 128) {
        float s = g_stats[slot1 * 256 + t], q = g_stats[slot1 * 256 + 128 + t];
        float mean = s * (1.f / CNT), var = q * (1.f / CNT) - mean * mean;
        float sc = g1[t] * rsqrtf(var + EPSV);
        s1[t] = sc; t1s[t] = be1[t] - mean * sc;
        s = g_stats[slot2 * 256 + t]; q = g_stats[slot2 * 256 + 128 + t];
        mean = s * (1.f / CNT); var = q * (1.f / CNT) - mean * mean;
        sc = g2[t] * rsqrtf(var + EPSV);
        s2[t] = sc; t2s[t] = be2[t] - mean * sc;
    }
    __syncthreads();
    float acc = 0.f, msum = 0.f;
    int r0 = seg * 128;
    for (int i = half; i < 128; i += 2) {
        int r = r0 + i;
        float m = mask[b * NN + r];
        float v = fmaf(s1[c], xa[(b * NN + r) * DD + c], t1s[c]) +
                  fmaf(s2[c], xb[(b * NN + r) * DD + c], t2s[c]);
        v = (v > 0.f) ? v : expm1f(v);
        acc += m * v;
        if (c == 0) msum += m;
    }
    __shared__ float red[256];
    red[t] = acc;
    __syncthreads();
    if (half == 0) atomicAdd(&g_pooled[b * DD + c], red[c] + red[c + 128]);
    __syncthreads();
    red[t] = (c == 0) ? msum : 0.f;
    __syncthreads();
    if (t == 0) atomicAdd(&g_den[b], red[0] + red[128]);
}

__global__ void out_kernel(const float* __restrict__ W2, const float* __restrict__ b2,
                           float* __restrict__ out) {
    int b = blockIdx.x, d = threadIdx.x;
    __shared__ float p[128];
    p[d] = g_pooled[b * DD + d];
    __syncthreads();
    float inv = 1.f / g_den[b];
    float accv = 0.f;
    #pragma unroll 4
    for (int c = 0; c < 128; c++) accv = fmaf(p[c], W2[c * 128 + d], accv);
    out[b * 128 + d] = accv * inv + b2[d];
}

// ---------------- host ----------------
extern "C" void kernel_launch(void* const* d_in, const int* in_sizes, int n_in,
                              void* d_out, int out_size) {
    const float* inputs = (const float*)d_in[0];
    const float* Lmat   = (const float*)d_in[1];
    const float* mask   = (const float*)d_in[2];
    const float* W1     = (const float*)d_in[3];
    const float* b1     = (const float*)d_in[4];
    const float* Wb     = (const float*)d_in[5];
    const float* bb     = (const float*)d_in[6];
    const float* gb     = (const float*)d_in[7];
    const float* beb    = (const float*)d_in[8];
    const float* g1     = (const float*)d_in[9];
    const float* be1    = (const float*)d_in[10];
    const float* g2     = (const float*)d_in[11];
    const float* be2    = (const float*)d_in[12];
    const float* W2     = (const float*)d_in[13];
    const float* b2     = (const float*)d_in[14];
    float* out = (float*)d_out;

    float *buf0, *buf1;
    cudaGetSymbolAddress((void**)&buf0, g_buf0);
    cudaGetSymbolAddress((void**)&buf1, g_buf1);

    cudaFuncSetAttribute(mma_gemm, cudaFuncAttributeMaxDynamicSharedMemorySize, MM_SMEM);
    cudaFuncSetAttribute(bnelu_mma, cudaFuncAttributeMaxDynamicSharedMemorySize, BM_SMEM);

    zero_stats_kernel<<<1, 256>>>();
    lconv_kernel<<<(BATCH * NN * NN) / 4 / 256, 256>>>(Lmat);
    wprep_all<<<NBLK, 256>>>(Wb);
    conv1_kernel<<<(BATCH * NN * DD) / 256, 256>>>(inputs, W1, b1);
    stats_kernel<<<256, 256>>>(buf0, 0);

    float* pa = buf0;   // x1
    float* pb = buf1;   // x2
    for (int k = 0; k < NBLK; k++) {
        dim3 grid(8, 16);
        bnelu_mma<<<grid, 256, BM_SMEM>>>(pa, k, gb + k * DD, beb + k * DD, k);
        mma_gemm<<<grid, 256, MM_SMEM>>>(pb, bb + k * DD, k + 1);
        float* tmp = pa; pa = pb; pb = tmp;
    }
    // pa = x1_final (stats slot 15), pb = x2_final (stats slot 14)
    dim3 pgrid(BATCH, 8);
    pool_kernel<<<pgrid, 256>>>(pa, pb, mask, g1, be1, g2, be2, NBLK, NBLK - 1);
    out_kernel<<<BATCH, 128>>>(W2, b2, out);
}